// round 3
// baseline (speedup 1.0000x reference)
#include <cuda_runtime.h>

typedef unsigned long long u64;

#define NTOK      262144      // B*T = 32*8192
#define DD        8
#define QQ        8
#define KK        1024
#define KH        512         // codeword pairs per stage
#define TPB       128
#define TOKS      2           // tokens per thread
#define NCTA      (NTOK / (TPB * TOKS))   // 1024
#define QUANT_N   (NTOK * DD)             // 2097152
#define LOSS_IDX  QUANT_N
#define CODES_OFF (QUANT_N + 1)

__device__ float g_loss_partial[NCTA];

static __device__ __forceinline__ u64 pk2(float lo, float hi) {
    u64 r; asm("mov.b64 %0, {%1, %2};" : "=l"(r) : "f"(lo), "f"(hi)); return r;
}
static __device__ __forceinline__ void upk2(u64 v, float &lo, float &hi) {
    asm("mov.b64 {%0, %1}, %2;" : "=f"(lo), "=f"(hi) : "l"(v));
}
static __device__ __forceinline__ float lof(u64 v) {
    float lo, hi; asm("mov.b64 {%0, %1}, %2;" : "=f"(lo), "=f"(hi) : "l"(v)); return lo;
}
static __device__ __forceinline__ u64 ffma2(u64 a, u64 b, u64 c) {
    u64 d; asm("fma.rn.f32x2 %0, %1, %2, %3;" : "=l"(d) : "l"(a), "l"(b), "l"(c)); return d;
}
static __device__ __forceinline__ u64 fmul2(u64 a, u64 b) {
    u64 d; asm("mul.rn.f32x2 %0, %1, %2;" : "=l"(d) : "l"(a), "l"(b)); return d;
}
static __device__ __forceinline__ u64 fadd2(u64 a, u64 b) {
    u64 d; asm("add.rn.f32x2 %0, %1, %2;" : "=l"(d) : "l"(a), "l"(b)); return d;
}

__global__ void __launch_bounds__(TPB, 4)
rvq_kernel(const float* __restrict__ x,
           const float* __restrict__ cbs,
           const float* __restrict__ ps,
           const float* __restrict__ pb,
           const float* __restrict__ convw,
           const float* __restrict__ convb,
           float* __restrict__ out)
{
    // codeword-pair-packed codebook: s_cw[p*8+d] = (c[2p][d], c[2p+1][d])
    __shared__ u64  s_cw[KH * DD];   // 32 KB
    __shared__ u64  s_c2[KH];        // 4 KB : (B_2p, B_2p+1), B = sum of rounded squares
    __shared__ float s_w[DD * DD];
    __shared__ float s_b[DD];
    __shared__ float s_red[TPB / 32];

    const int tid = threadIdx.x;
    const int t0  = blockIdx.x * (TPB * TOKS) + tid;
    const int t1  = t0 + TPB;

    if (tid < DD * DD) s_w[tid] = convw[tid];
    if (tid < DD)      s_b[tid] = convb[tid];

    // residual state: m[d] = packed(r_d, r_d)
    u64 m0[DD], m1[DD];
    float qs0[DD], qs1[DD];
    float A0, A1;     // |r|^2, computed exactly as reference: square-then-sequential-add
    {
        float4 a = *(const float4*)(x + (size_t)t0 * DD);
        float4 b = *(const float4*)(x + (size_t)t0 * DD + 4);
        float4 c = *(const float4*)(x + (size_t)t1 * DD);
        float4 d = *(const float4*)(x + (size_t)t1 * DD + 4);
        float r0[DD] = {a.x, a.y, a.z, a.w, b.x, b.y, b.z, b.w};
        float r1[DD] = {c.x, c.y, c.z, c.w, d.x, d.y, d.z, d.w};
        A0 = r0[0] * r0[0];
        A1 = r1[0] * r1[0];
        #pragma unroll
        for (int d2 = 1; d2 < DD; ++d2) {
            A0 = A0 + r0[d2] * r0[d2];   // fl(square) then add, ascending
            A1 = A1 + r1[d2] * r1[d2];
        }
        #pragma unroll
        for (int d2 = 0; d2 < DD; ++d2) {
            m0[d2] = pk2(r0[d2], r0[d2]);
            m1[d2] = pk2(r1[d2], r1[d2]);
            qs0[d2] = 0.0f;
            qs1[d2] = 0.0f;
        }
    }

    float ls = 0.0f;
    const float INF  = __int_as_float(0x7f800000);
    const u64  NEG2  = pk2(-2.0f, -2.0f);

    for (int q = 0; q < QQ; ++q) {
        __syncthreads();   // protect previous stage's s_cw reads

        // ---- stage codebook into packed smem ----
        const float* cb = cbs + (size_t)q * KK * DD;
        for (int p = tid; p < KH; p += TPB) {
            const float4* cp = (const float4*)(cb + (size_t)p * 16);
            float4 u0 = cp[0], u1 = cp[1];   // codeword 2p
            float4 v0 = cp[2], v1 = cp[3];   // codeword 2p+1
            float c0[DD] = {u0.x, u0.y, u0.z, u0.w, u1.x, u1.y, u1.z, u1.w};
            float c1[DD] = {v0.x, v0.y, v0.z, v0.w, v1.x, v1.y, v1.z, v1.w};
            // B_k = (cb**2).sum(-1): round each square, then sequential add
            float n0 = c0[0] * c0[0];
            float n1 = c1[0] * c1[0];
            #pragma unroll
            for (int d = 1; d < DD; ++d) {
                n0 = n0 + c0[d] * c0[d];
                n1 = n1 + c1[d] * c1[d];
            }
            #pragma unroll
            for (int d = 0; d < DD; ++d)
                s_cw[p * DD + d] = pk2(c0[d], c1[d]);
            s_c2[p] = pk2(n0, n1);
        }
        __syncthreads();

        // ---- 1024-way argmin of fl(fl(A+B_k) - 2*E_k), E_k ascending fma chain ----
        float b0 = INF, b1 = INF;
        int   i0 = 0,   i1 = 0;
        const u64 A2_0 = pk2(A0, A0);
        const u64 A2_1 = pk2(A1, A1);

        #pragma unroll 2
        for (int kk = 0; kk < KH; ++kk) {
            u64 w0 = s_cw[kk * DD + 0];
            u64 e0 = fmul2(m0[0], w0);     // == fma(r0,c0,0) rounding
            u64 e1 = fmul2(m1[0], w0);
            #pragma unroll
            for (int d = 1; d < DD; ++d) {
                u64 w = s_cw[kk * DD + d];
                e0 = ffma2(m0[d], w, e0);
                e1 = ffma2(m1[d], w, e1);
            }
            u64 c2 = s_c2[kk];
            u64 ab0 = fadd2(A2_0, c2);           // fl(A + B)
            u64 ab1 = fadd2(A2_1, c2);
            u64 d0 = ffma2(e0, NEG2, ab0);       // == fl((A+B) - 2E)  (2E exact)
            u64 d1 = ffma2(e1, NEG2, ab1);

            float dl0, dh0, dl1, dh1;
            upk2(d0, dl0, dh0);
            upk2(d1, dl1, dh1);
            if (dl0 < b0) { b0 = dl0; i0 = 2 * kk; }
            if (dh0 < b0) { b0 = dh0; i0 = 2 * kk + 1; }
            if (dl1 < b1) { b1 = dl1; i1 = 2 * kk; }
            if (dh1 < b1) { b1 = dh1; i1 = 2 * kk + 1; }
        }

        const float sq = ps[q];
        const float bq = pb[q];

        // ---- token updates, reference rounding order ----
        {
            int p = i0 >> 1, hi = i0 & 1;
            float newA = 0.0f;
            #pragma unroll
            for (int d = 0; d < DD; ++d) {
                float clo, chi; upk2(s_cw[p * DD + d], clo, chi);
                float c = hi ? chi : clo;
                float r = lof(m0[d]);
                // qsum = (qsum + embeds*s) + b
                qs0[d] = (qs0[d] + c * sq) + bq;
                float rn = r - c;            // new_res (exact ref op)
                float t  = rn - c;           // stop_grad(new_res) - embeds
                ls = fmaf(t, t, ls);
                float sqr = rn * rn;
                newA = (d == 0) ? sqr : (newA + sqr);
                m0[d] = pk2(rn, rn);
            }
            A0 = newA;
        }
        {
            int p = i1 >> 1, hi = i1 & 1;
            float newA = 0.0f;
            #pragma unroll
            for (int d = 0; d < DD; ++d) {
                float clo, chi; upk2(s_cw[p * DD + d], clo, chi);
                float c = hi ? chi : clo;
                float r = lof(m1[d]);
                qs1[d] = (qs1[d] + c * sq) + bq;
                float rn = r - c;
                float t  = rn - c;
                ls = fmaf(t, t, ls);
                float sqr = rn * rn;
                newA = (d == 0) ? sqr : (newA + sqr);
                m1[d] = pk2(rn, rn);
            }
            A1 = newA;
        }

        out[CODES_OFF + (size_t)q * NTOK + t0] = (float)i0;
        out[CODES_OFF + (size_t)q * NTOK + t1] = (float)i1;
    }

    // ---- final 1x1 conv: quantized[e] = sum_d qsum[d]*w[e][d] + b[e] ----
    {
        float o0[DD], o1[DD];
        #pragma unroll
        for (int e = 0; e < DD; ++e) {
            float a0 = qs0[0] * s_w[e * DD];
            float a1 = qs1[0] * s_w[e * DD];
            #pragma unroll
            for (int d = 1; d < DD; ++d) {
                a0 = fmaf(qs0[d], s_w[e * DD + d], a0);
                a1 = fmaf(qs1[d], s_w[e * DD + d], a1);
            }
            o0[e] = a0 + s_b[e];
            o1[e] = a1 + s_b[e];
        }
        *(float4*)(out + (size_t)t0 * DD)     = make_float4(o0[0], o0[1], o0[2], o0[3]);
        *(float4*)(out + (size_t)t0 * DD + 4) = make_float4(o0[4], o0[5], o0[6], o0[7]);
        *(float4*)(out + (size_t)t1 * DD)     = make_float4(o1[0], o1[1], o1[2], o1[3]);
        *(float4*)(out + (size_t)t1 * DD + 4) = make_float4(o1[4], o1[5], o1[6], o1[7]);
    }

    // ---- deterministic loss reduction ----
    #pragma unroll
    for (int off = 16; off > 0; off >>= 1)
        ls += __shfl_down_sync(0xffffffffu, ls, off);
    if ((tid & 31) == 0) s_red[tid >> 5] = ls;
    __syncthreads();
    if (tid == 0)
        g_loss_partial[blockIdx.x] = (s_red[0] + s_red[1]) + (s_red[2] + s_red[3]);
}

__global__ void __launch_bounds__(256)
loss_finalize(float* __restrict__ out)
{
    __shared__ float sh[256];
    int tid = threadIdx.x;
    float v = (g_loss_partial[tid]       + g_loss_partial[tid + 256])
            + (g_loss_partial[tid + 512] + g_loss_partial[tid + 768]);
    sh[tid] = v;
    __syncthreads();
    #pragma unroll
    for (int s = 128; s > 0; s >>= 1) {
        if (tid < s) sh[tid] += sh[tid + s];
        __syncthreads();
    }
    if (tid == 0)
        out[LOSS_IDX] = sh[0] * (0.25f / 2097152.0f);  // * COMMITMENT_COST / (B*T*D)
}

extern "C" void kernel_launch(void* const* d_in, const int* in_sizes, int n_in,
                              void* d_out, int out_size)
{
    const float* x     = (const float*)d_in[0];
    const float* cbs   = (const float*)d_in[1];
    const float* psc   = (const float*)d_in[2];
    const float* pbs   = (const float*)d_in[3];
    const float* convw = (const float*)d_in[4];
    const float* convb = (const float*)d_in[5];
    float* out = (float*)d_out;

    rvq_kernel<<<NCTA, TPB>>>(x, cbs, psc, pbs, convw, convb, out);
    loss_finalize<<<1, 256>>>(out);
}

// round 4
// speedup vs baseline: 1.0310x; 1.0310x over previous
#include <cuda_runtime.h>

typedef unsigned long long u64;

#define NTOK      262144      // B*T = 32*8192
#define DD        8
#define QQ        8
#define KK        1024
#define KH        512         // codeword pairs per stage
#define TPB       128
#define TOKS      2           // tokens per thread
#define NCTA      (NTOK / (TPB * TOKS))   // 1024
#define QUANT_N   (NTOK * DD)             // 2097152
#define LOSS_IDX  QUANT_N
#define CODES_OFF (QUANT_N + 1)

__device__ float g_loss_partial[NCTA];
__device__ int   g_ctr = 0;

static __device__ __forceinline__ u64 pk2(float lo, float hi) {
    u64 r; asm("mov.b64 %0, {%1, %2};" : "=l"(r) : "f"(lo), "f"(hi)); return r;
}
static __device__ __forceinline__ void upk2(u64 v, float &lo, float &hi) {
    asm("mov.b64 {%0, %1}, %2;" : "=f"(lo), "=f"(hi) : "l"(v));
}
static __device__ __forceinline__ float lof(u64 v) {
    float lo, hi; asm("mov.b64 {%0, %1}, %2;" : "=f"(lo), "=f"(hi) : "l"(v)); return lo;
}
static __device__ __forceinline__ u64 ffma2(u64 a, u64 b, u64 c) {
    u64 d; asm("fma.rn.f32x2 %0, %1, %2, %3;" : "=l"(d) : "l"(a), "l"(b), "l"(c)); return d;
}
static __device__ __forceinline__ u64 fmul2(u64 a, u64 b) {
    u64 d; asm("mul.rn.f32x2 %0, %1, %2;" : "=l"(d) : "l"(a), "l"(b)); return d;
}
static __device__ __forceinline__ u64 fadd2(u64 a, u64 b) {
    u64 d; asm("add.rn.f32x2 %0, %1, %2;" : "=l"(d) : "l"(a), "l"(b)); return d;
}

__global__ void __launch_bounds__(TPB, 4)
rvq_kernel(const float* __restrict__ x,
           const float* __restrict__ cbs,
           const float* __restrict__ ps,
           const float* __restrict__ pb,
           const float* __restrict__ convw,
           const float* __restrict__ convb,
           float* __restrict__ out)
{
    // codeword-pair-packed codebook: s_cw[p*8+d] = (c[2p][d], c[2p+1][d])
    __shared__ u64  s_cw[KH * DD];   // 32 KB, rows 64B-aligned
    __shared__ u64  s_c2[KH];        // 4 KB : (B_2p, B_2p+1)
    __shared__ float s_w[DD * DD];
    __shared__ float s_b[DD];
    __shared__ float s_red[TPB / 32];
    __shared__ int   s_last;

    const int tid = threadIdx.x;
    const int t0  = blockIdx.x * (TPB * TOKS) + tid;
    const int t1  = t0 + TPB;

    if (tid < DD * DD) s_w[tid] = convw[tid];
    if (tid < DD)      s_b[tid] = convb[tid];

    // residual state: m[d] = packed(r_d, r_d)
    u64 m0[DD], m1[DD];
    float qs0[DD], qs1[DD];
    float A0, A1;     // |r|^2, square-then-sequential-add (reference order)
    {
        float4 a = *(const float4*)(x + (size_t)t0 * DD);
        float4 b = *(const float4*)(x + (size_t)t0 * DD + 4);
        float4 c = *(const float4*)(x + (size_t)t1 * DD);
        float4 d = *(const float4*)(x + (size_t)t1 * DD + 4);
        float r0[DD] = {a.x, a.y, a.z, a.w, b.x, b.y, b.z, b.w};
        float r1[DD] = {c.x, c.y, c.z, c.w, d.x, d.y, d.z, d.w};
        A0 = r0[0] * r0[0];
        A1 = r1[0] * r1[0];
        #pragma unroll
        for (int d2 = 1; d2 < DD; ++d2) {
            A0 = A0 + r0[d2] * r0[d2];
            A1 = A1 + r1[d2] * r1[d2];
        }
        #pragma unroll
        for (int d2 = 0; d2 < DD; ++d2) {
            m0[d2] = pk2(r0[d2], r0[d2]);
            m1[d2] = pk2(r1[d2], r1[d2]);
            qs0[d2] = 0.0f;
            qs1[d2] = 0.0f;
        }
    }

    float ls = 0.0f;
    const float INF  = __int_as_float(0x7f800000);
    const u64  NEG2  = pk2(-2.0f, -2.0f);

    for (int q = 0; q < QQ; ++q) {
        __syncthreads();   // protect previous stage's s_cw reads

        // ---- stage codebook into packed smem ----
        const float* cb = cbs + (size_t)q * KK * DD;
        for (int p = tid; p < KH; p += TPB) {
            const float4* cp = (const float4*)(cb + (size_t)p * 16);
            float4 u0 = cp[0], u1 = cp[1];   // codeword 2p
            float4 v0 = cp[2], v1 = cp[3];   // codeword 2p+1
            float c0[DD] = {u0.x, u0.y, u0.z, u0.w, u1.x, u1.y, u1.z, u1.w};
            float c1[DD] = {v0.x, v0.y, v0.z, v0.w, v1.x, v1.y, v1.z, v1.w};
            // B_k = (cb**2).sum(-1): round each square, then sequential add
            float n0 = c0[0] * c0[0];
            float n1 = c1[0] * c1[0];
            #pragma unroll
            for (int d = 1; d < DD; ++d) {
                n0 = n0 + c0[d] * c0[d];
                n1 = n1 + c1[d] * c1[d];
            }
            #pragma unroll
            for (int d = 0; d < DD; ++d)
                s_cw[p * DD + d] = pk2(c0[d], c1[d]);
            s_c2[p] = pk2(n0, n1);
        }
        __syncthreads();

        // ---- 1024-way argmin of fl(fl(A+B_k) - 2*E_k), E ascending fma chain ----
        float b0 = INF, b1 = INF;
        int   i0 = 0,   i1 = 0;
        const u64 A2_0 = pk2(A0, A0);
        const u64 A2_1 = pk2(A1, A1);

        #pragma unroll 4
        for (int kk = 0; kk < KH; ++kk) {
            // vectorized codeword fetch: 4x LDS.128 (broadcast, conflict-free)
            ulonglong2 wa = *(const ulonglong2*)(s_cw + kk * DD + 0);
            ulonglong2 wb = *(const ulonglong2*)(s_cw + kk * DD + 2);
            ulonglong2 wc = *(const ulonglong2*)(s_cw + kk * DD + 4);
            ulonglong2 wd = *(const ulonglong2*)(s_cw + kk * DD + 6);

            u64 e0 = fmul2(m0[0], wa.x);
            u64 e1 = fmul2(m1[0], wa.x);
            e0 = ffma2(m0[1], wa.y, e0);  e1 = ffma2(m1[1], wa.y, e1);
            e0 = ffma2(m0[2], wb.x, e0);  e1 = ffma2(m1[2], wb.x, e1);
            e0 = ffma2(m0[3], wb.y, e0);  e1 = ffma2(m1[3], wb.y, e1);
            e0 = ffma2(m0[4], wc.x, e0);  e1 = ffma2(m1[4], wc.x, e1);
            e0 = ffma2(m0[5], wc.y, e0);  e1 = ffma2(m1[5], wc.y, e1);
            e0 = ffma2(m0[6], wd.x, e0);  e1 = ffma2(m1[6], wd.x, e1);
            e0 = ffma2(m0[7], wd.y, e0);  e1 = ffma2(m1[7], wd.y, e1);

            u64 c2 = s_c2[kk];
            u64 ab0 = fadd2(A2_0, c2);           // fl(A + B)
            u64 ab1 = fadd2(A2_1, c2);
            u64 d0 = ffma2(e0, NEG2, ab0);       // fl((A+B) - 2E), 2E exact
            u64 d1 = ffma2(e1, NEG2, ab1);

            float dl0, dh0, dl1, dh1;
            upk2(d0, dl0, dh0);
            upk2(d1, dl1, dh1);
            if (dl0 < b0) { b0 = dl0; i0 = 2 * kk; }
            if (dh0 < b0) { b0 = dh0; i0 = 2 * kk + 1; }
            if (dl1 < b1) { b1 = dl1; i1 = 2 * kk; }
            if (dh1 < b1) { b1 = dh1; i1 = 2 * kk + 1; }
        }

        const float sq = ps[q];
        const float bq = pb[q];

        // ---- token updates, reference rounding order ----
        {
            int p = i0 >> 1, hi = i0 & 1;
            float newA = 0.0f;
            #pragma unroll
            for (int d = 0; d < DD; ++d) {
                float clo, chi; upk2(s_cw[p * DD + d], clo, chi);
                float c = hi ? chi : clo;
                float r = lof(m0[d]);
                qs0[d] = (qs0[d] + c * sq) + bq;     // (qsum + e*s) + b
                float rn = r - c;                     // new_res
                float t  = rn - c;                    // sg(new_res) - embeds
                ls = fmaf(t, t, ls);
                float sqr = rn * rn;
                newA = (d == 0) ? sqr : (newA + sqr);
                m0[d] = pk2(rn, rn);
            }
            A0 = newA;
        }
        {
            int p = i1 >> 1, hi = i1 & 1;
            float newA = 0.0f;
            #pragma unroll
            for (int d = 0; d < DD; ++d) {
                float clo, chi; upk2(s_cw[p * DD + d], clo, chi);
                float c = hi ? chi : clo;
                float r = lof(m1[d]);
                qs1[d] = (qs1[d] + c * sq) + bq;
                float rn = r - c;
                float t  = rn - c;
                ls = fmaf(t, t, ls);
                float sqr = rn * rn;
                newA = (d == 0) ? sqr : (newA + sqr);
                m1[d] = pk2(rn, rn);
            }
            A1 = newA;
        }

        out[CODES_OFF + (size_t)q * NTOK + t0] = (float)i0;
        out[CODES_OFF + (size_t)q * NTOK + t1] = (float)i1;
    }

    // ---- final 1x1 conv ----
    {
        float o0[DD], o1[DD];
        #pragma unroll
        for (int e = 0; e < DD; ++e) {
            float a0 = qs0[0] * s_w[e * DD];
            float a1 = qs1[0] * s_w[e * DD];
            #pragma unroll
            for (int d = 1; d < DD; ++d) {
                a0 = fmaf(qs0[d], s_w[e * DD + d], a0);
                a1 = fmaf(qs1[d], s_w[e * DD + d], a1);
            }
            o0[e] = a0 + s_b[e];
            o1[e] = a1 + s_b[e];
        }
        *(float4*)(out + (size_t)t0 * DD)     = make_float4(o0[0], o0[1], o0[2], o0[3]);
        *(float4*)(out + (size_t)t0 * DD + 4) = make_float4(o0[4], o0[5], o0[6], o0[7]);
        *(float4*)(out + (size_t)t1 * DD)     = make_float4(o1[0], o1[1], o1[2], o1[3]);
        *(float4*)(out + (size_t)t1 * DD + 4) = make_float4(o1[4], o1[5], o1[6], o1[7]);
    }

    // ---- deterministic per-CTA loss partial ----
    #pragma unroll
    for (int off = 16; off > 0; off >>= 1)
        ls += __shfl_down_sync(0xffffffffu, ls, off);
    if ((tid & 31) == 0) s_red[tid >> 5] = ls;
    __syncthreads();
    if (tid == 0) {
        g_loss_partial[blockIdx.x] = (s_red[0] + s_red[1]) + (s_red[2] + s_red[3]);
        __threadfence();
        int old = atomicAdd(&g_ctr, 1);
        s_last = (old == NCTA - 1) ? 1 : 0;
    }
    __syncthreads();

    // ---- last CTA: fixed-order global loss reduction (deterministic) ----
    if (s_last) {
        __threadfence();   // acquire: make all partials visible
        float v = 0.0f;
        #pragma unroll
        for (int j = 0; j < NCTA / TPB; ++j)    // 8 strided, fixed order
            v += g_loss_partial[tid + j * TPB];
        #pragma unroll
        for (int off = 16; off > 0; off >>= 1)
            v += __shfl_down_sync(0xffffffffu, v, off);
        if ((tid & 31) == 0) s_red[tid >> 5] = v;
        __syncthreads();
        if (tid == 0) {
            float tot = (s_red[0] + s_red[1]) + (s_red[2] + s_red[3]);
            out[LOSS_IDX] = tot * (0.25f / 2097152.0f);  // * COMMITMENT_COST / (B*T*D)
            g_ctr = 0;     // reset for next graph replay
        }
    }
}

extern "C" void kernel_launch(void* const* d_in, const int* in_sizes, int n_in,
                              void* d_out, int out_size)
{
    const float* x     = (const float*)d_in[0];
    const float* cbs   = (const float*)d_in[1];
    const float* psc   = (const float*)d_in[2];
    const float* pbs   = (const float*)d_in[3];
    const float* convw = (const float*)d_in[4];
    const float* convb = (const float*)d_in[5];
    float* out = (float*)d_out;

    rvq_kernel<<<NCTA, TPB>>>(x, cbs, psc, pbs, convw, convb, out);
}

// round 5
// speedup vs baseline: 1.0764x; 1.0441x over previous
#include <cuda_runtime.h>

typedef unsigned long long u64;

#define NTOK      262144      // B*T = 32*8192
#define DD        8
#define QQ        8
#define KK        1024
#define KH        512         // codeword pairs per stage
#define TPB       128
#define TOKS      2           // tokens per thread
#define NCTA      (NTOK / (TPB * TOKS))   // 1024
#define QUANT_N   (NTOK * DD)             // 2097152
#define LOSS_IDX  QUANT_N
#define CODES_OFF (QUANT_N + 1)

__device__ float g_loss_partial[NCTA];
__device__ int   g_ctr = 0;

static __device__ __forceinline__ u64 pk2(float lo, float hi) {
    u64 r; asm("mov.b64 %0, {%1, %2};" : "=l"(r) : "f"(lo), "f"(hi)); return r;
}
static __device__ __forceinline__ void upk2(u64 v, float &lo, float &hi) {
    asm("mov.b64 {%0, %1}, %2;" : "=f"(lo), "=f"(hi) : "l"(v));
}
static __device__ __forceinline__ float lof(u64 v) {
    float lo, hi; asm("mov.b64 {%0, %1}, %2;" : "=f"(lo), "=f"(hi) : "l"(v)); return lo;
}
static __device__ __forceinline__ u64 ffma2(u64 a, u64 b, u64 c) {
    u64 d; asm("fma.rn.f32x2 %0, %1, %2, %3;" : "=l"(d) : "l"(a), "l"(b), "l"(c)); return d;
}
static __device__ __forceinline__ u64 fmul2(u64 a, u64 b) {
    u64 d; asm("mul.rn.f32x2 %0, %1, %2;" : "=l"(d) : "l"(a), "l"(b)); return d;
}
static __device__ __forceinline__ u64 fadd2(u64 a, u64 b) {
    u64 d; asm("add.rn.f32x2 %0, %1, %2;" : "=l"(d) : "l"(a), "l"(b)); return d;
}
// unpack f32x2 halves directly as int bit patterns (positive floats: signed-int
// compare == float compare; argmin runs on the ALU pipe, lat-4 ISETP->SEL/IMNMX)
static __device__ __forceinline__ void upk2i(u64 v, int &lo, int &hi) {
    asm("mov.b64 {%0, %1}, %2;" : "=r"(lo), "=r"(hi) : "l"(v));
}

__global__ void __launch_bounds__(TPB, 4)
rvq_kernel(const float* __restrict__ x,
           const float* __restrict__ cbs,
           const float* __restrict__ ps,
           const float* __restrict__ pb,
           const float* __restrict__ convw,
           const float* __restrict__ convb,
           float* __restrict__ out)
{
    // codeword-pair-packed codebook: s_cw[p*8+d] = (c[2p][d], c[2p+1][d])
    __shared__ u64  s_cw[KH * DD];   // 32 KB
    __shared__ u64  s_c2[KH];        // 4 KB : (B_2p, B_2p+1)
    __shared__ float s_w[DD * DD];
    __shared__ float s_b[DD];
    __shared__ float s_red[TPB / 32];
    __shared__ int   s_last;

    const int tid = threadIdx.x;
    const int t0  = blockIdx.x * (TPB * TOKS) + tid;
    const int t1  = t0 + TPB;

    if (tid < DD * DD) s_w[tid] = convw[tid];
    if (tid < DD)      s_b[tid] = convb[tid];

    // residual state: m[d] = packed(r_d, r_d)
    u64 m0[DD], m1[DD];
    float qs0[DD], qs1[DD];
    float A0, A1;     // |r|^2, square-then-sequential-add (reference order)
    {
        float4 a = *(const float4*)(x + (size_t)t0 * DD);
        float4 b = *(const float4*)(x + (size_t)t0 * DD + 4);
        float4 c = *(const float4*)(x + (size_t)t1 * DD);
        float4 d = *(const float4*)(x + (size_t)t1 * DD + 4);
        float r0[DD] = {a.x, a.y, a.z, a.w, b.x, b.y, b.z, b.w};
        float r1[DD] = {c.x, c.y, c.z, c.w, d.x, d.y, d.z, d.w};
        A0 = r0[0] * r0[0];
        A1 = r1[0] * r1[0];
        #pragma unroll
        for (int d2 = 1; d2 < DD; ++d2) {
            A0 = A0 + r0[d2] * r0[d2];
            A1 = A1 + r1[d2] * r1[d2];
        }
        #pragma unroll
        for (int d2 = 0; d2 < DD; ++d2) {
            m0[d2] = pk2(r0[d2], r0[d2]);
            m1[d2] = pk2(r1[d2], r1[d2]);
            qs0[d2] = 0.0f;
            qs1[d2] = 0.0f;
        }
    }

    float ls = 0.0f;
    const int  INFB  = 0x7f800000;       // +inf bits
    const u64  NEG2  = pk2(-2.0f, -2.0f);

    for (int q = 0; q < QQ; ++q) {
        __syncthreads();   // protect previous stage's s_cw reads

        // ---- stage codebook into packed smem ----
        const float* cb = cbs + (size_t)q * KK * DD;
        for (int p = tid; p < KH; p += TPB) {
            const float4* cp = (const float4*)(cb + (size_t)p * 16);
            float4 u0 = cp[0], u1 = cp[1];   // codeword 2p
            float4 v0 = cp[2], v1 = cp[3];   // codeword 2p+1
            float c0[DD] = {u0.x, u0.y, u0.z, u0.w, u1.x, u1.y, u1.z, u1.w};
            float c1[DD] = {v0.x, v0.y, v0.z, v0.w, v1.x, v1.y, v1.z, v1.w};
            // B_k = (cb**2).sum(-1): round each square, then sequential add
            float n0 = c0[0] * c0[0];
            float n1 = c1[0] * c1[0];
            #pragma unroll
            for (int d = 1; d < DD; ++d) {
                n0 = n0 + c0[d] * c0[d];
                n1 = n1 + c1[d] * c1[d];
            }
            #pragma unroll
            for (int d = 0; d < DD; ++d)
                s_cw[p * DD + d] = pk2(c0[d], c1[d]);
            s_c2[p] = pk2(n0, n1);
        }
        __syncthreads();

        // ---- 1024-way argmin of fl(fl(A+B_k) - 2*E_k) ----
        // 4 independent min chains: (even,odd) x (tok0,tok1); int-domain compares.
        int blb0 = INFB, bhb0 = INFB, il0 = 0, ih0 = 0;
        int blb1 = INFB, bhb1 = INFB, il1 = 0, ih1 = 0;
        const u64 A2_0 = pk2(A0, A0);
        const u64 A2_1 = pk2(A1, A1);

        #pragma unroll 4
        for (int kk = 0; kk < KH; ++kk) {
            ulonglong2 wa = *(const ulonglong2*)(s_cw + kk * DD + 0);
            ulonglong2 wb = *(const ulonglong2*)(s_cw + kk * DD + 2);
            ulonglong2 wc = *(const ulonglong2*)(s_cw + kk * DD + 4);
            ulonglong2 wd = *(const ulonglong2*)(s_cw + kk * DD + 6);

            u64 e0 = fmul2(m0[0], wa.x);
            u64 e1 = fmul2(m1[0], wa.x);
            e0 = ffma2(m0[1], wa.y, e0);  e1 = ffma2(m1[1], wa.y, e1);
            e0 = ffma2(m0[2], wb.x, e0);  e1 = ffma2(m1[2], wb.x, e1);
            e0 = ffma2(m0[3], wb.y, e0);  e1 = ffma2(m1[3], wb.y, e1);
            e0 = ffma2(m0[4], wc.x, e0);  e1 = ffma2(m1[4], wc.x, e1);
            e0 = ffma2(m0[5], wc.y, e0);  e1 = ffma2(m1[5], wc.y, e1);
            e0 = ffma2(m0[6], wd.x, e0);  e1 = ffma2(m1[6], wd.x, e1);
            e0 = ffma2(m0[7], wd.y, e0);  e1 = ffma2(m1[7], wd.y, e1);

            u64 c2 = s_c2[kk];
            u64 ab0 = fadd2(A2_0, c2);           // fl(A + B)
            u64 ab1 = fadd2(A2_1, c2);
            u64 d0 = ffma2(e0, NEG2, ab0);       // fl((A+B) - 2E), 2E exact
            u64 d1 = ffma2(e1, NEG2, ab1);

            int dl0, dh0, dl1, dh1;
            upk2i(d0, dl0, dh0);
            upk2i(d1, dl1, dh1);
            // independent lat-4 chains: ISETP -> SEL (pred-as-data) + IMNMX
            il0  = (dl0 < blb0) ? kk : il0;   blb0 = min(blb0, dl0);
            ih0  = (dh0 < bhb0) ? kk : ih0;   bhb0 = min(bhb0, dh0);
            il1  = (dl1 < blb1) ? kk : il1;   blb1 = min(blb1, dl1);
            ih1  = (dh1 < bhb1) ? kk : ih1;   bhb1 = min(bhb1, dh1);
        }

        // exact first-min merge (jnp.argmin semantics, handles fp-equal ties)
        int i0, i1;
        if (bhb0 < blb0)        i0 = 2 * ih0 + 1;
        else if (bhb0 == blb0)  i0 = (il0 <= ih0) ? 2 * il0 : 2 * ih0 + 1;
        else                    i0 = 2 * il0;
        if (bhb1 < blb1)        i1 = 2 * ih1 + 1;
        else if (bhb1 == blb1)  i1 = (il1 <= ih1) ? 2 * il1 : 2 * ih1 + 1;
        else                    i1 = 2 * il1;

        const float sq = ps[q];
        const float bq = pb[q];

        // ---- token updates, reference rounding order ----
        {
            int p = i0 >> 1, hi = i0 & 1;
            float newA = 0.0f;
            #pragma unroll
            for (int d = 0; d < DD; ++d) {
                float clo, chi; upk2(s_cw[p * DD + d], clo, chi);
                float c = hi ? chi : clo;
                float r = lof(m0[d]);
                qs0[d] = (qs0[d] + c * sq) + bq;     // (qsum + e*s) + b
                float rn = r - c;                     // new_res
                float t  = rn - c;                    // sg(new_res) - embeds
                ls = fmaf(t, t, ls);
                float sqr = rn * rn;
                newA = (d == 0) ? sqr : (newA + sqr);
                m0[d] = pk2(rn, rn);
            }
            A0 = newA;
        }
        {
            int p = i1 >> 1, hi = i1 & 1;
            float newA = 0.0f;
            #pragma unroll
            for (int d = 0; d < DD; ++d) {
                float clo, chi; upk2(s_cw[p * DD + d], clo, chi);
                float c = hi ? chi : clo;
                float r = lof(m1[d]);
                qs1[d] = (qs1[d] + c * sq) + bq;
                float rn = r - c;
                float t  = rn - c;
                ls = fmaf(t, t, ls);
                float sqr = rn * rn;
                newA = (d == 0) ? sqr : (newA + sqr);
                m1[d] = pk2(rn, rn);
            }
            A1 = newA;
        }

        out[CODES_OFF + (size_t)q * NTOK + t0] = (float)i0;
        out[CODES_OFF + (size_t)q * NTOK + t1] = (float)i1;
    }

    // ---- final 1x1 conv ----
    {
        float o0[DD], o1[DD];
        #pragma unroll
        for (int e = 0; e < DD; ++e) {
            float a0 = qs0[0] * s_w[e * DD];
            float a1 = qs1[0] * s_w[e * DD];
            #pragma unroll
            for (int d = 1; d < DD; ++d) {
                a0 = fmaf(qs0[d], s_w[e * DD + d], a0);
                a1 = fmaf(qs1[d], s_w[e * DD + d], a1);
            }
            o0[e] = a0 + s_b[e];
            o1[e] = a1 + s_b[e];
        }
        *(float4*)(out + (size_t)t0 * DD)     = make_float4(o0[0], o0[1], o0[2], o0[3]);
        *(float4*)(out + (size_t)t0 * DD + 4) = make_float4(o0[4], o0[5], o0[6], o0[7]);
        *(float4*)(out + (size_t)t1 * DD)     = make_float4(o1[0], o1[1], o1[2], o1[3]);
        *(float4*)(out + (size_t)t1 * DD + 4) = make_float4(o1[4], o1[5], o1[6], o1[7]);
    }

    // ---- deterministic per-CTA loss partial ----
    #pragma unroll
    for (int off = 16; off > 0; off >>= 1)
        ls += __shfl_down_sync(0xffffffffu, ls, off);
    if ((tid & 31) == 0) s_red[tid >> 5] = ls;
    __syncthreads();
    if (tid == 0) {
        g_loss_partial[blockIdx.x] = (s_red[0] + s_red[1]) + (s_red[2] + s_red[3]);
        __threadfence();
        int old = atomicAdd(&g_ctr, 1);
        s_last = (old == NCTA - 1) ? 1 : 0;
    }
    __syncthreads();

    // ---- last CTA: fixed-order global loss reduction (deterministic) ----
    if (s_last) {
        __threadfence();
        float v = 0.0f;
        #pragma unroll
        for (int j = 0; j < NCTA / TPB; ++j)
            v += g_loss_partial[tid + j * TPB];
        #pragma unroll
        for (int off = 16; off > 0; off >>= 1)
            v += __shfl_down_sync(0xffffffffu, v, off);
        if ((tid & 31) == 0) s_red[tid >> 5] = v;
        __syncthreads();
        if (tid == 0) {
            float tot = (s_red[0] + s_red[1]) + (s_red[2] + s_red[3]);
            out[LOSS_IDX] = tot * (0.25f / 2097152.0f);  // * COMMITMENT_COST / (B*T*D)
            g_ctr = 0;     // reset for next graph replay
        }
    }
}

extern "C" void kernel_launch(void* const* d_in, const int* in_sizes, int n_in,
                              void* d_out, int out_size)
{
    const float* x     = (const float*)d_in[0];
    const float* cbs   = (const float*)d_in[1];
    const float* psc   = (const float*)d_in[2];
    const float* pbs   = (const float*)d_in[3];
    const float* convw = (const float*)d_in[4];
    const float* convb = (const float*)d_in[5];
    float* out = (float*)d_out;

    rvq_kernel<<<NCTA, TPB>>>(x, cbs, psc, pbs, convw, convb, out);
}